// round 15
// baseline (speedup 1.0000x reference)
#include <cuda_runtime.h>
#include <cuda_bf16.h>

#define NUM_CLASSES 1000
#define VEC_PER_ROW 250          // 1000 floats / 4
#define ROWS_PER_BLOCK 8         // 8 warps per 256-thread block, 1 warp per row
#define MAX_BLOCKS 16384

// Per-block partial sums of (1 - win). Static device scratch (no allocation).
__device__ double g_partials[MAX_BLOCKS];

__global__ __launch_bounds__(256, 8) void hloss_main(
    const float* __restrict__ outputs,
    const int*   __restrict__ target,
    int B)
{
    const int warp = threadIdx.x >> 5;
    const int lane = threadIdx.x & 31;
    const int row  = blockIdx.x * ROWS_PER_BLOCK + warp;

    float one_minus_win = 0.0f;

    if (row < B) {
        const float* rowp = outputs + (size_t)row * NUM_CLASSES;
        const float4* r4  = reinterpret_cast<const float4*>(rowp);

        // ---- main streaming sum: 250 float4 per row, lane-strided ----
        float s0 = 0.f, s1 = 0.f, s2 = 0.f, s3 = 0.f;
        #pragma unroll
        for (int i = 0; i < 7; i++) {
            float4 x = r4[lane + 32 * i];
            s0 += x.x; s1 += x.y; s2 += x.z; s3 += x.w;
        }
        if (lane < VEC_PER_ROW - 7 * 32) {   // lanes 0..25 handle the tail
            float4 x = r4[lane + 224];
            s0 += x.x; s1 += x.y; s2 += x.z; s3 += x.w;
        }
        float sall = (s0 + s1) + (s2 + s3);

        // ---- hierarchy-local terms (all L1-hot re-reads) ----
        const int t = target[row];
        const int g = t / 100;   // 100-leaf block id
        const int h = t / 10;    // 10-leaf block id

        // 100-block: 25 aligned float4s, weight 0.25
        float s100 = 0.f;
        if (lane < 25) {
            float4 x = r4[g * 25 + lane];
            s100 = (x.x + x.y) + (x.z + x.w);
        }

        // 10-block (weight 0.125) + extra target term (another 0.125 on c==t)
        float s10t = 0.f;
        if (lane < 10) {
            int c = h * 10 + lane;
            float x = rowp[c];
            s10t = x * ((c == t) ? 0.25f : 0.125f);
        }

        // per-lane contribution to win (weights distribute over the lane sum)
        float v = 0.5f * sall + 0.25f * s100 + s10t;

        // warp reduction -> win for this row
        #pragma unroll
        for (int o = 16; o > 0; o >>= 1)
            v += __shfl_xor_sync(0xffffffffu, v, o);

        if (lane == 0) one_minus_win = 1.0f - v;
    }

    // ---- block reduction of the 8 per-row (1 - win) values ----
    __shared__ float sh[ROWS_PER_BLOCK];
    if (lane == 0) sh[warp] = one_minus_win;
    __syncthreads();
    if (threadIdx.x == 0) {
        float bs = 0.f;
        #pragma unroll
        for (int w = 0; w < ROWS_PER_BLOCK; w++) bs += sh[w];
        g_partials[blockIdx.x] = (double)bs;
    }
}

__global__ __launch_bounds__(256) void hloss_reduce(float* __restrict__ out, int nblocks)
{
    double s = 0.0;
    for (int i = threadIdx.x; i < nblocks; i += 256)
        s += g_partials[i];

    // warp reduce (double)
    #pragma unroll
    for (int o = 16; o > 0; o >>= 1)
        s += __shfl_down_sync(0xffffffffu, s, o);

    __shared__ double sh[8];
    const int warp = threadIdx.x >> 5;
    const int lane = threadIdx.x & 31;
    if (lane == 0) sh[warp] = s;
    __syncthreads();
    if (threadIdx.x == 0) {
        double tot = 0.0;
        #pragma unroll
        for (int w = 0; w < 8; w++) tot += sh[w];
        out[0] = (float)tot;
    }
}

extern "C" void kernel_launch(void* const* d_in, const int* in_sizes, int n_in,
                              void* d_out, int out_size)
{
    const float* outputs = (const float*)d_in[0];   // [B, 1000] fp32
    const int*   target  = (const int*)d_in[1];     // [B] int32
    const int B = in_sizes[1];

    int nblocks = (B + ROWS_PER_BLOCK - 1) / ROWS_PER_BLOCK;
    if (nblocks > MAX_BLOCKS) nblocks = MAX_BLOCKS;  // B<=131072 covered; bench B=32768 -> 4096

    hloss_main<<<nblocks, 256>>>(outputs, target, B);
    hloss_reduce<<<1, 256>>>((float*)d_out, nblocks);
}